// round 5
// baseline (speedup 1.0000x reference)
#include <cuda_runtime.h>
#include <math.h>

#define BATCH   8
#define NPTS    4096
#define SPLITS  4
#define SCAND   (NPTS / SPLITS)   // 1024 candidates per split
#define TILE    256
#define BLOCK   64
#define Q       4
#define QPB     (BLOCK * Q)       // 256 queries per block
#define QCHUNKS (NPTS / 256)      // 16 query chunks per (dir,b)

// Scratch (static device arrays; no allocation allowed)
__device__ float  g_part [2 * BATCH * QCHUNKS];           // partial |diff|^5 sums
__device__ float  g_pbest[2 * BATCH * NPTS * SPLITS];
__device__ int    g_pidx [2 * BATCH * NPTS * SPLITS];

// Bit-exact rescore used by both the main loop and the rescan.
static __device__ __forceinline__ float score(float cx, float cy, float cz,
                                              float nqx, float nqy, float nqz) {
    float h = 0.5f * fmaf(cx, cx, fmaf(cy, cy, cz * cz));
    return fmaf(nqx, cx, fmaf(nqy, cy, fmaf(nqz, cz, h)));
}

static __device__ __forceinline__ int rescan32(const float* __restrict__ dbb, int base,
                                               float nqx, float nqy, float nqz, float best) {
    for (int j = 0; j < 32; j++) {
        int c = base + j;
        float d = score(dbb[c * 3 + 0], dbb[c * 3 + 1], dbb[c * 3 + 2], nqx, nqy, nqz);
        if (d == best) return c;   // first exact match = first min occurrence
    }
    return base;  // unreachable
}

// Each thread: 4 queries, scanning this block's candidate split.
// Argmin objective: h - q.c, h = 0.5|c|^2 (|q|^2 dropped, argmin-invariant).
__global__ void __launch_bounds__(BLOCK) chamfer_main(
    const float* __restrict__ x, const float* __restrict__ y)
{
    const int qchunk = blockIdx.x >> 2;   // 0..15
    const int split  = blockIdx.x & 3;    // 0..3
    const int b   = blockIdx.y;
    const int dir = blockIdx.z;
    const float* q  = (dir == 0) ? x : y;
    const float* db = (dir == 0) ? y : x;
    const float* qb  = q  + (size_t)b * NPTS * 3;
    const float* dbb = db + (size_t)b * NPTS * 3;

    const int i0 = qchunk * QPB + threadIdx.x;
    const int i1 = i0 + BLOCK;
    const int i2 = i0 + 2 * BLOCK;
    const int i3 = i0 + 3 * BLOCK;

    const float nqx0 = -qb[i0*3+0], nqy0 = -qb[i0*3+1], nqz0 = -qb[i0*3+2];
    const float nqx1 = -qb[i1*3+0], nqy1 = -qb[i1*3+1], nqz1 = -qb[i1*3+2];
    const float nqx2 = -qb[i2*3+0], nqy2 = -qb[i2*3+1], nqz2 = -qb[i2*3+2];
    const float nqx3 = -qb[i3*3+0], nqy3 = -qb[i3*3+1], nqz3 = -qb[i3*3+2];

    __shared__ float4 sh[TILE];

    float best0 = 3.4e38f, best1 = 3.4e38f, best2 = 3.4e38f, best3 = 3.4e38f;
    const int cbeg = split * SCAND;
    int base0 = cbeg, base1 = cbeg, base2 = cbeg, base3 = cbeg;

    for (int t = 0; t < SCAND; t += TILE) {
        __syncthreads();
        #pragma unroll
        for (int k = 0; k < TILE / BLOCK; k++) {
            const int cl = threadIdx.x + k * BLOCK;
            const int c  = cbeg + t + cl;
            float cx = dbb[c*3+0], cy = dbb[c*3+1], cz = dbb[c*3+2];
            sh[cl] = make_float4(cx, cy, cz, 0.5f * fmaf(cx, cx, fmaf(cy, cy, cz * cz)));
        }
        __syncthreads();

        #pragma unroll
        for (int g = 0; g < TILE / 32; g++) {
            const float p0 = best0, p1 = best1, p2 = best2, p3 = best3;
            #pragma unroll 8
            for (int j = 0; j < 32; j++) {
                float4 c = sh[g * 32 + j];   // broadcast LDS.128
                best0 = fminf(best0, fmaf(nqx0, c.x, fmaf(nqy0, c.y, fmaf(nqz0, c.z, c.w))));
                best1 = fminf(best1, fmaf(nqx1, c.x, fmaf(nqy1, c.y, fmaf(nqz1, c.z, c.w))));
                best2 = fminf(best2, fmaf(nqx2, c.x, fmaf(nqy2, c.y, fmaf(nqz2, c.z, c.w))));
                best3 = fminf(best3, fmaf(nqx3, c.x, fmaf(nqy3, c.y, fmaf(nqz3, c.z, c.w))));
            }
            const int gb = cbeg + t + g * 32;
            // Strict < keeps the EARLIEST group containing the running min.
            if (best0 < p0) base0 = gb;
            if (best1 < p1) base1 = gb;
            if (best2 < p2) base2 = gb;
            if (best3 < p3) base3 = gb;
        }
    }

    // Recover exact indices (bit-exact recompute within the recorded group).
    const int idx0 = rescan32(dbb, base0, nqx0, nqy0, nqz0, best0);
    const int idx1 = rescan32(dbb, base1, nqx1, nqy1, nqz1, best1);
    const int idx2 = rescan32(dbb, base2, nqx2, nqy2, nqz2, best2);
    const int idx3 = rescan32(dbb, base3, nqx3, nqy3, nqz3, best3);

    const int qs = (dir * BATCH + b) * NPTS;
    g_pbest[(qs + i0) * SPLITS + split] = best0;  g_pidx[(qs + i0) * SPLITS + split] = idx0;
    g_pbest[(qs + i1) * SPLITS + split] = best1;  g_pidx[(qs + i1) * SPLITS + split] = idx1;
    g_pbest[(qs + i2) * SPLITS + split] = best2;  g_pidx[(qs + i2) * SPLITS + split] = idx2;
    g_pbest[(qs + i3) * SPLITS + split] = best3;  g_pidx[(qs + i3) * SPLITS + split] = idx3;
}

// One block per 256 queries of one (dir, b): pick winning split, gather NN,
// block-reduce sum |diff|^5, write one partial (no atomics).
__global__ void __launch_bounds__(256) combine_kernel(
    const float* __restrict__ x, const float* __restrict__ y)
{
    const int chunk = blockIdx.x;
    const int b   = blockIdx.y;
    const int dir = blockIdx.z;
    const int qi  = chunk * 256 + threadIdx.x;
    const float* q  = (dir == 0) ? x : y;
    const float* db = (dir == 0) ? y : x;
    const float* qb  = q  + (size_t)b * NPTS * 3;
    const float* dbb = db + (size_t)b * NPTS * 3;

    const int slot = ((dir * BATCH + b) * NPTS + qi) * SPLITS;
    float bb = g_pbest[slot];
    int   bi = g_pidx[slot];
    #pragma unroll
    for (int s = 1; s < SPLITS; s++) {
        float v = g_pbest[slot + s];   // strict < : earlier split wins ties
        if (v < bb) { bb = v; bi = g_pidx[slot + s]; }
    }

    float qx = qb[qi*3+0], qy = qb[qi*3+1], qz = qb[qi*3+2];
    float nx = dbb[bi*3+0], ny = dbb[bi*3+1], nz = dbb[bi*3+2];
    float ax = fabsf(qx - nx), ay = fabsf(qy - ny), az = fabsf(qz - nz);
    float ax2 = ax * ax, ay2 = ay * ay, az2 = az * az;
    float v = ax2 * ax2 * ax + ay2 * ay2 * ay + az2 * az2 * az;

    __shared__ float red[256];
    red[threadIdx.x] = v;
    __syncthreads();
    #pragma unroll
    for (int stride = 128; stride >= 32; stride >>= 1) {
        if (threadIdx.x < stride) red[threadIdx.x] += red[threadIdx.x + stride];
        __syncthreads();
    }
    if (threadIdx.x < 32) {
        float r = red[threadIdx.x];
        #pragma unroll
        for (int off = 16; off > 0; off >>= 1)
            r += __shfl_down_sync(0xFFFFFFFF, r, off);
        if (threadIdx.x == 0)
            g_part[(dir * BATCH + b) * QCHUNKS + chunk] = r;
    }
}

// 256 threads: reduce 16 chunk-partials per (dir,b), take ^(1/5) in parallel
// (float powf ~200 cyc vs single-thread double pow chain ~80K cyc), mean over B.
__global__ void __launch_bounds__(256) final_kernel(float* __restrict__ out) {
    __shared__ float sp[256];
    __shared__ float roots[2 * BATCH];
    sp[threadIdx.x] = g_part[threadIdx.x];
    __syncthreads();
    if (threadIdx.x < 2 * BATCH) {
        float s = 0.0f;
        #pragma unroll
        for (int c = 0; c < QCHUNKS; c++) s += sp[threadIdx.x * QCHUNKS + c];
        roots[threadIdx.x] = powf(s, 0.2f);
    }
    __syncthreads();
    if (threadIdx.x == 0) {
        float acc = 0.0f;
        #pragma unroll
        for (int i = 0; i < 2 * BATCH; i++) acc += roots[i];
        out[0] = acc / (float)BATCH;
    }
}

extern "C" void kernel_launch(void* const* d_in, const int* in_sizes, int n_in,
                              void* d_out, int out_size)
{
    const float* x = (const float*)d_in[0];
    const float* y = (const float*)d_in[1];
    float* out = (float*)d_out;

    dim3 grid(16 * SPLITS, BATCH, 2);   // 64 x 8 x 2 = 1024 blocks
    chamfer_main<<<grid, BLOCK>>>(x, y);

    dim3 cgrid(QCHUNKS, BATCH, 2);      // 16 x 8 x 2 = 256 blocks
    combine_kernel<<<cgrid, 256>>>(x, y);

    final_kernel<<<1, 256>>>(out);
}

// round 6
// speedup vs baseline: 1.8658x; 1.8658x over previous
#include <cuda_runtime.h>
#include <math.h>

#define BATCH   8
#define NPTS    4096
#define SPLITS  16
#define SCAND   (NPTS / SPLITS)   // 256 candidates per split = one tile
#define TILE    256
#define BLOCK   64
#define Q       8
#define QPB     (BLOCK * Q)       // 512 queries per block
#define QCHUNKS_MAIN (NPTS / QPB) // 8
#define QCHUNKS (NPTS / 256)      // 16 (combine granularity)

// Scratch (static device arrays; no allocation allowed)
__device__ float  g_part [2 * BATCH * QCHUNKS];            // partial |diff|^5 sums
__device__ float  g_pbest[2 * BATCH * NPTS * SPLITS];      // per-split best score
__device__ int    g_pbase[2 * BATCH * NPTS * SPLITS];      // per-split 32-group base

// Bit-exact rescore (identical fmaf sequence to the main loop / tile prep).
static __device__ __forceinline__ float score(float cx, float cy, float cz,
                                              float nqx, float nqy, float nqz) {
    float h = 0.5f * fmaf(cx, cx, fmaf(cy, cy, cz * cz));
    return fmaf(nqx, cx, fmaf(nqy, cy, fmaf(nqz, cz, h)));
}

// Main: each thread owns 8 queries, scans this block's 256-candidate split.
// Objective: h - q.c, h = 0.5|c|^2 (|q|^2 dropped, argmin-invariant).
// Records (best, base-of-32-group containing first min); exact index recovered later.
__global__ void __launch_bounds__(BLOCK) chamfer_main(
    const float* __restrict__ x, const float* __restrict__ y)
{
    const int qchunk = blockIdx.x >> 4;    // 0..7
    const int split  = blockIdx.x & 15;    // 0..15
    const int b   = blockIdx.y;
    const int dir = blockIdx.z;
    const float* q  = (dir == 0) ? x : y;
    const float* db = (dir == 0) ? y : x;
    const float* qb  = q  + (size_t)b * NPTS * 3;
    const float* dbb = db + (size_t)b * NPTS * 3;

    int qi[Q];
    float nqx[Q], nqy[Q], nqz[Q];
    #pragma unroll
    for (int k = 0; k < Q; k++) {
        qi[k] = qchunk * QPB + threadIdx.x + k * BLOCK;
        nqx[k] = -qb[qi[k]*3+0];
        nqy[k] = -qb[qi[k]*3+1];
        nqz[k] = -qb[qi[k]*3+2];
    }

    __shared__ float4 sh[TILE];

    const int cbeg = split * SCAND;
    // Load this split's tile (64 threads x 4 candidates each).
    #pragma unroll
    for (int k = 0; k < TILE / BLOCK; k++) {
        const int cl = threadIdx.x + k * BLOCK;
        const int c  = cbeg + cl;
        float cx = dbb[c*3+0], cy = dbb[c*3+1], cz = dbb[c*3+2];
        sh[cl] = make_float4(cx, cy, cz, 0.5f * fmaf(cx, cx, fmaf(cy, cy, cz * cz)));
    }
    __syncthreads();

    float best[Q];
    int   base[Q];
    #pragma unroll
    for (int k = 0; k < Q; k++) { best[k] = 3.4e38f; base[k] = cbeg; }

    #pragma unroll
    for (int g = 0; g < TILE / 32; g++) {
        float prev[Q];
        #pragma unroll
        for (int k = 0; k < Q; k++) prev[k] = best[k];
        #pragma unroll 8
        for (int j = 0; j < 32; j++) {
            float4 c = sh[g * 32 + j];   // broadcast LDS.128, feeds 8 chains
            #pragma unroll
            for (int k = 0; k < Q; k++)
                best[k] = fminf(best[k],
                    fmaf(nqx[k], c.x, fmaf(nqy[k], c.y, fmaf(nqz[k], c.z, c.w))));
        }
        const int gb = cbeg + g * 32;
        #pragma unroll
        for (int k = 0; k < Q; k++)
            if (best[k] < prev[k]) base[k] = gb;   // strict <: earliest group wins
    }

    const int qs = (dir * BATCH + b) * NPTS;
    #pragma unroll
    for (int k = 0; k < Q; k++) {
        g_pbest[(qs + qi[k]) * SPLITS + split] = best[k];
        g_pbase[(qs + qi[k]) * SPLITS + split] = base[k];
    }
}

// Combine: pick winning split (strict <, ascending order => global-first tie),
// rescan its 32-group for the exact index (bit-exact recompute, first match),
// gather NN, block-reduce sum |diff|^5, write one partial per chunk.
__global__ void __launch_bounds__(256) combine_kernel(
    const float* __restrict__ x, const float* __restrict__ y)
{
    const int chunk = blockIdx.x;
    const int b   = blockIdx.y;
    const int dir = blockIdx.z;
    const int qi  = chunk * 256 + threadIdx.x;
    const float* q  = (dir == 0) ? x : y;
    const float* db = (dir == 0) ? y : x;
    const float* qb  = q  + (size_t)b * NPTS * 3;
    const float* dbb = db + (size_t)b * NPTS * 3;

    const int slot = ((dir * BATCH + b) * NPTS + qi) * SPLITS;
    float bb = g_pbest[slot];
    int   base = g_pbase[slot];
    #pragma unroll
    for (int s = 1; s < SPLITS; s++) {
        float v = g_pbest[slot + s];
        if (v < bb) { bb = v; base = g_pbase[slot + s]; }
    }

    const float qx = qb[qi*3+0], qy = qb[qi*3+1], qz = qb[qi*3+2];
    const float nqxv = -qx, nqyv = -qy, nqzv = -qz;

    int bi = base;
    #pragma unroll 4
    for (int j = 0; j < 32; j++) {
        int c = base + j;
        float d = score(dbb[c*3+0], dbb[c*3+1], dbb[c*3+2], nqxv, nqyv, nqzv);
        if (d == bb) { bi = c; break; }   // first exact match = first min
    }

    float nx = dbb[bi*3+0], ny = dbb[bi*3+1], nz = dbb[bi*3+2];
    float ax = fabsf(qx - nx), ay = fabsf(qy - ny), az = fabsf(qz - nz);
    float ax2 = ax * ax, ay2 = ay * ay, az2 = az * az;
    float v = ax2 * ax2 * ax + ay2 * ay2 * ay + az2 * az2 * az;

    __shared__ float red[256];
    red[threadIdx.x] = v;
    __syncthreads();
    #pragma unroll
    for (int stride = 128; stride >= 32; stride >>= 1) {
        if (threadIdx.x < stride) red[threadIdx.x] += red[threadIdx.x + stride];
        __syncthreads();
    }
    if (threadIdx.x < 32) {
        float r = red[threadIdx.x];
        #pragma unroll
        for (int off = 16; off > 0; off >>= 1)
            r += __shfl_down_sync(0xFFFFFFFF, r, off);
        if (threadIdx.x == 0)
            g_part[(dir * BATCH + b) * QCHUNKS + chunk] = r;
    }
}

// Reduce 16 chunk-partials per (dir,b), ^(1/5) in parallel, mean over B.
__global__ void __launch_bounds__(256) final_kernel(float* __restrict__ out) {
    __shared__ float sp[256];
    __shared__ float roots[2 * BATCH];
    sp[threadIdx.x] = g_part[threadIdx.x];
    __syncthreads();
    if (threadIdx.x < 2 * BATCH) {
        float s = 0.0f;
        #pragma unroll
        for (int c = 0; c < QCHUNKS; c++) s += sp[threadIdx.x * QCHUNKS + c];
        roots[threadIdx.x] = powf(s, 0.2f);
    }
    __syncthreads();
    if (threadIdx.x == 0) {
        float acc = 0.0f;
        #pragma unroll
        for (int i = 0; i < 2 * BATCH; i++) acc += roots[i];
        out[0] = acc / (float)BATCH;
    }
}

extern "C" void kernel_launch(void* const* d_in, const int* in_sizes, int n_in,
                              void* d_out, int out_size)
{
    const float* x = (const float*)d_in[0];
    const float* y = (const float*)d_in[1];
    float* out = (float*)d_out;

    dim3 grid(QCHUNKS_MAIN * SPLITS, BATCH, 2);   // 128 x 8 x 2 = 2048 blocks
    chamfer_main<<<grid, BLOCK>>>(x, y);

    dim3 cgrid(QCHUNKS, BATCH, 2);                // 16 x 8 x 2 = 256 blocks
    combine_kernel<<<cgrid, 256>>>(x, y);

    final_kernel<<<1, 256>>>(out);
}

// round 7
// speedup vs baseline: 1.8739x; 1.0044x over previous
#include <cuda_runtime.h>
#include <math.h>

#define BATCH   8
#define NPTS    4096
#define SPLITS  16
#define SCAND   (NPTS / SPLITS)   // 256 candidates per split = one tile
#define TILE    256
#define BLOCK   64
#define Q       8                 // queries per thread (4 packed f32x2 pairs)
#define NP      (Q / 2)
#define QPB     (BLOCK * Q)       // 512 queries per block
#define QCHUNKS_MAIN (NPTS / QPB) // 8
#define QCHUNKS (NPTS / 256)      // 16 (combine granularity)

// Scratch (static device arrays; no allocation allowed)
__device__ float  g_part [2 * BATCH * QCHUNKS];            // partial |diff|^5 sums
__device__ float  g_pbest[2 * BATCH * NPTS * SPLITS];      // per-split best score
__device__ int    g_pbase[2 * BATCH * NPTS * SPLITS];      // per-split 32-group base

static __device__ __forceinline__ unsigned long long pack2(float a, float b) {
    unsigned long long r;
    asm("mov.b64 %0, {%1, %2};" : "=l"(r) : "f"(a), "f"(b));
    return r;
}
static __device__ __forceinline__ unsigned long long fma2(
    unsigned long long a, unsigned long long b, unsigned long long c) {
    unsigned long long r;
    asm("fma.rn.f32x2 %0, %1, %2, %3;" : "=l"(r) : "l"(a), "l"(b), "l"(c));
    return r;
}
static __device__ __forceinline__ void unpack2(unsigned long long v, float& lo, float& hi) {
    asm("mov.b64 {%0, %1}, %2;" : "=f"(lo), "=f"(hi) : "l"(v));
}

// Bit-exact scalar rescore. Chain order matches the packed per-lane order:
// fma(nqx,cx, fma(nqy,cy, fma(nqz,cz,h))), h = 0.5*fma(cx,cx,fma(cy,cy,cz*cz)).
static __device__ __forceinline__ float score(float cx, float cy, float cz,
                                              float nqx, float nqy, float nqz) {
    float h = 0.5f * fmaf(cx, cx, fmaf(cy, cy, cz * cz));
    return fmaf(nqx, cx, fmaf(nqy, cy, fmaf(nqz, cz, h)));
}

// Main: each thread owns 8 queries (4 f32x2 pairs), scans a 256-candidate split.
// Objective: h - q.c (|q|^2 dropped, argmin-invariant). Records per-split
// (best, base-of-32-group of first min); exact index recovered in combine.
__global__ void __launch_bounds__(BLOCK) chamfer_main(
    const float* __restrict__ x, const float* __restrict__ y)
{
    const int qchunk = blockIdx.x >> 4;    // 0..7
    const int split  = blockIdx.x & 15;    // 0..15
    const int b   = blockIdx.y;
    const int dir = blockIdx.z;
    const float* q  = (dir == 0) ? x : y;
    const float* db = (dir == 0) ? y : x;
    const float* qb  = q  + (size_t)b * NPTS * 3;
    const float* dbb = db + (size_t)b * NPTS * 3;

    // Packed negated query components: pair p covers queries (2p, 2p+1).
    unsigned long long nqx[NP], nqy[NP], nqz[NP];
    #pragma unroll
    for (int p = 0; p < NP; p++) {
        const int ia = qchunk * QPB + threadIdx.x + (2 * p) * BLOCK;
        const int ib = ia + BLOCK;
        nqx[p] = pack2(-qb[ia*3+0], -qb[ib*3+0]);
        nqy[p] = pack2(-qb[ia*3+1], -qb[ib*3+1]);
        nqz[p] = pack2(-qb[ia*3+2], -qb[ib*3+2]);
    }

    // Duplicated candidate layout (32 B/cand): shA[j]=(cx,cx,cy,cy), shB[j]=(cz,cz,h,h)
    __shared__ ulonglong2 shA[TILE];
    __shared__ ulonglong2 shB[TILE];

    const int cbeg = split * SCAND;
    #pragma unroll
    for (int k = 0; k < TILE / BLOCK; k++) {
        const int cl = threadIdx.x + k * BLOCK;
        const int c  = cbeg + cl;
        float cx = dbb[c*3+0], cy = dbb[c*3+1], cz = dbb[c*3+2];
        float h  = 0.5f * fmaf(cx, cx, fmaf(cy, cy, cz * cz));
        ulonglong2 A, B;
        A.x = pack2(cx, cx);  A.y = pack2(cy, cy);
        B.x = pack2(cz, cz);  B.y = pack2(h, h);
        shA[cl] = A;
        shB[cl] = B;
    }
    __syncthreads();

    float best[Q];
    int   base[Q];
    #pragma unroll
    for (int k = 0; k < Q; k++) { best[k] = 3.4e38f; base[k] = cbeg; }

    #pragma unroll
    for (int g = 0; g < TILE / 32; g++) {
        float prev[Q];
        #pragma unroll
        for (int k = 0; k < Q; k++) prev[k] = best[k];
        #pragma unroll 8
        for (int j = 0; j < 32; j++) {
            ulonglong2 A = shA[g * 32 + j];   // broadcast LDS.128
            ulonglong2 B = shB[g * 32 + j];   // broadcast LDS.128
            #pragma unroll
            for (int p = 0; p < NP; p++) {
                unsigned long long acc = fma2(nqz[p], B.x, B.y);
                acc = fma2(nqy[p], A.y, acc);
                acc = fma2(nqx[p], A.x, acc);
                float lo, hi;
                unpack2(acc, lo, hi);          // register-pair aliasing, ~free
                best[2*p]   = fminf(best[2*p],   lo);
                best[2*p+1] = fminf(best[2*p+1], hi);
            }
        }
        const int gb = cbeg + g * 32;
        #pragma unroll
        for (int k = 0; k < Q; k++)
            if (best[k] < prev[k]) base[k] = gb;   // strict <: earliest group wins
    }

    const int qs = (dir * BATCH + b) * NPTS;
    #pragma unroll
    for (int k = 0; k < Q; k++) {
        // query index for slot k: pair p=k/2, half k%2 -> (2p + half)*BLOCK offset
        const int qidx = qchunk * QPB + threadIdx.x + k * BLOCK;
        g_pbest[(qs + qidx) * SPLITS + split] = best[k];
        g_pbase[(qs + qidx) * SPLITS + split] = base[k];
    }
}

// Combine: pick winning split (strict <, ascending => global-first tie), rescan
// its 32-group (bit-exact, first match), gather NN, reduce sum |diff|^5.
__global__ void __launch_bounds__(256) combine_kernel(
    const float* __restrict__ x, const float* __restrict__ y)
{
    const int chunk = blockIdx.x;
    const int b   = blockIdx.y;
    const int dir = blockIdx.z;
    const int qi  = chunk * 256 + threadIdx.x;
    const float* q  = (dir == 0) ? x : y;
    const float* db = (dir == 0) ? y : x;
    const float* qb  = q  + (size_t)b * NPTS * 3;
    const float* dbb = db + (size_t)b * NPTS * 3;

    const int slot = ((dir * BATCH + b) * NPTS + qi) * SPLITS;
    float bb  = g_pbest[slot];
    int   base = g_pbase[slot];
    #pragma unroll
    for (int s = 1; s < SPLITS; s++) {
        float v = g_pbest[slot + s];
        if (v < bb) { bb = v; base = g_pbase[slot + s]; }
    }

    const float qx = qb[qi*3+0], qy = qb[qi*3+1], qz = qb[qi*3+2];
    const float nqxv = -qx, nqyv = -qy, nqzv = -qz;

    int bi = base;
    #pragma unroll 4
    for (int j = 0; j < 32; j++) {
        int c = base + j;
        float d = score(dbb[c*3+0], dbb[c*3+1], dbb[c*3+2], nqxv, nqyv, nqzv);
        if (d == bb) { bi = c; break; }   // first exact match = first min
    }

    float nx = dbb[bi*3+0], ny = dbb[bi*3+1], nz = dbb[bi*3+2];
    float ax = fabsf(qx - nx), ay = fabsf(qy - ny), az = fabsf(qz - nz);
    float ax2 = ax * ax, ay2 = ay * ay, az2 = az * az;
    float v = ax2 * ax2 * ax + ay2 * ay2 * ay + az2 * az2 * az;

    __shared__ float red[256];
    red[threadIdx.x] = v;
    __syncthreads();
    #pragma unroll
    for (int stride = 128; stride >= 32; stride >>= 1) {
        if (threadIdx.x < stride) red[threadIdx.x] += red[threadIdx.x + stride];
        __syncthreads();
    }
    if (threadIdx.x < 32) {
        float r = red[threadIdx.x];
        #pragma unroll
        for (int off = 16; off > 0; off >>= 1)
            r += __shfl_down_sync(0xFFFFFFFF, r, off);
        if (threadIdx.x == 0)
            g_part[(dir * BATCH + b) * QCHUNKS + chunk] = r;
    }
}

// Reduce 16 chunk-partials per (dir,b), ^(1/5) in parallel, mean over B.
__global__ void __launch_bounds__(256) final_kernel(float* __restrict__ out) {
    __shared__ float sp[256];
    __shared__ float roots[2 * BATCH];
    sp[threadIdx.x] = g_part[threadIdx.x];
    __syncthreads();
    if (threadIdx.x < 2 * BATCH) {
        float s = 0.0f;
        #pragma unroll
        for (int c = 0; c < QCHUNKS; c++) s += sp[threadIdx.x * QCHUNKS + c];
        roots[threadIdx.x] = powf(s, 0.2f);
    }
    __syncthreads();
    if (threadIdx.x == 0) {
        float acc = 0.0f;
        #pragma unroll
        for (int i = 0; i < 2 * BATCH; i++) acc += roots[i];
        out[0] = acc / (float)BATCH;
    }
}

extern "C" void kernel_launch(void* const* d_in, const int* in_sizes, int n_in,
                              void* d_out, int out_size)
{
    const float* x = (const float*)d_in[0];
    const float* y = (const float*)d_in[1];
    float* out = (float*)d_out;

    dim3 grid(QCHUNKS_MAIN * SPLITS, BATCH, 2);   // 128 x 8 x 2 = 2048 blocks
    chamfer_main<<<grid, BLOCK>>>(x, y);

    dim3 cgrid(QCHUNKS, BATCH, 2);                // 16 x 8 x 2 = 256 blocks
    combine_kernel<<<cgrid, 256>>>(x, y);

    final_kernel<<<1, 256>>>(out);
}

// round 8
// speedup vs baseline: 1.9044x; 1.0163x over previous
#include <cuda_runtime.h>
#include <math.h>

#define BATCH   8
#define NPTS    4096
#define SPLITS  16
#define SCAND   (NPTS / SPLITS)   // 256 candidates per split = one tile
#define TILE    256
#define BLOCK   64
#define Q       8                 // queries per thread
#define QPB     (BLOCK * Q)       // 512 queries per block
#define QCHUNKS_MAIN (NPTS / QPB) // 8
#define QCHUNKS (NPTS / 256)      // 16 (combine granularity)
#define NCOMBINE (QCHUNKS * BATCH * 2)  // 256 combine blocks

// Scratch (static device arrays; no allocation allowed)
__device__ unsigned long long g_pack[2 * BATCH * NPTS * SPLITS]; // (score|base) packed
__device__ float g_part[NCOMBINE];                               // per-chunk |diff|^5 sums
__device__ unsigned int g_ticket;                                // zero-init, self-resetting

// Order-preserving float -> uint32 map (monotone for all finite floats).
static __device__ __forceinline__ unsigned int fmap(float f) {
    unsigned int u = __float_as_uint(f);
    return (u & 0x80000000u) ? ~u : (u | 0x80000000u);
}
static __device__ __forceinline__ float funmap(unsigned int m) {
    return __uint_as_float((m & 0x80000000u) ? (m & 0x7FFFFFFFu) : ~m);
}

// Bit-exact rescore (identical fmaf sequence to the main loop / tile prep).
static __device__ __forceinline__ float score(float cx, float cy, float cz,
                                              float nqx, float nqy, float nqz) {
    float h = 0.5f * fmaf(cx, cx, fmaf(cy, cy, cz * cz));
    return fmaf(nqx, cx, fmaf(nqy, cy, fmaf(nqz, cz, h)));
}

// Main: each thread owns 8 queries, scans this block's 256-candidate split.
// Objective: h - q.c, h = 0.5|c|^2 (|q|^2 dropped, argmin-invariant).
// Writes one packed u64 per (query, split): [mapped score | 32-group base].
__global__ void __launch_bounds__(BLOCK) chamfer_main(
    const float* __restrict__ x, const float* __restrict__ y)
{
    const int qchunk = blockIdx.x >> 4;    // 0..7
    const int split  = blockIdx.x & 15;    // 0..15
    const int b   = blockIdx.y;
    const int dir = blockIdx.z;
    const float* q  = (dir == 0) ? x : y;
    const float* db = (dir == 0) ? y : x;
    const float* qb  = q  + (size_t)b * NPTS * 3;
    const float* dbb = db + (size_t)b * NPTS * 3;

    float nqx[Q], nqy[Q], nqz[Q];
    #pragma unroll
    for (int k = 0; k < Q; k++) {
        const int qi = qchunk * QPB + threadIdx.x + k * BLOCK;
        nqx[k] = -qb[qi*3+0];
        nqy[k] = -qb[qi*3+1];
        nqz[k] = -qb[qi*3+2];
    }

    __shared__ float4 sh[TILE];

    const int cbeg = split * SCAND;
    #pragma unroll
    for (int k = 0; k < TILE / BLOCK; k++) {
        const int cl = threadIdx.x + k * BLOCK;
        const int c  = cbeg + cl;
        float cx = dbb[c*3+0], cy = dbb[c*3+1], cz = dbb[c*3+2];
        sh[cl] = make_float4(cx, cy, cz, 0.5f * fmaf(cx, cx, fmaf(cy, cy, cz * cz)));
    }
    __syncthreads();

    float best[Q];
    int   base[Q];
    #pragma unroll
    for (int k = 0; k < Q; k++) { best[k] = 3.4e38f; base[k] = cbeg; }

    #pragma unroll
    for (int g = 0; g < TILE / 32; g++) {
        float prev[Q];
        #pragma unroll
        for (int k = 0; k < Q; k++) prev[k] = best[k];
        #pragma unroll 8
        for (int j = 0; j < 32; j++) {
            float4 c = sh[g * 32 + j];   // broadcast LDS.128, feeds 8 chains
            #pragma unroll
            for (int k = 0; k < Q; k++)
                best[k] = fminf(best[k],
                    fmaf(nqx[k], c.x, fmaf(nqy[k], c.y, fmaf(nqz[k], c.z, c.w))));
        }
        const int gb = cbeg + g * 32;
        #pragma unroll
        for (int k = 0; k < Q; k++)
            if (best[k] < prev[k]) base[k] = gb;   // strict <: earliest group wins
    }

    const int qs = (dir * BATCH + b) * NPTS;
    #pragma unroll
    for (int k = 0; k < Q; k++) {
        const int qi = qchunk * QPB + threadIdx.x + k * BLOCK;
        g_pack[(qs + qi) * SPLITS + split] =
            ((unsigned long long)fmap(best[k]) << 32) | (unsigned int)base[k];
    }
}

// Combine: branchless u64 min over 16 splits (equal score bits -> smaller base
// = earlier candidate wins, matching first-min), rescan winning 32-group
// (bit-exact, first match), gather NN, reduce sum |diff|^5 per chunk.
// LAST block (ticket) folds the final reduction: sums chunk partials per
// (dir,b), takes ^(1/5), means over B, writes out[0], resets ticket.
__global__ void __launch_bounds__(256) combine_kernel(
    const float* __restrict__ x, const float* __restrict__ y,
    float* __restrict__ out)
{
    const int chunk = blockIdx.x;
    const int b   = blockIdx.y;
    const int dir = blockIdx.z;
    const int qi  = chunk * 256 + threadIdx.x;
    const float* q  = (dir == 0) ? x : y;
    const float* db = (dir == 0) ? y : x;
    const float* qb  = q  + (size_t)b * NPTS * 3;
    const float* dbb = db + (size_t)b * NPTS * 3;

    const int slot = ((dir * BATCH + b) * NPTS + qi) * SPLITS;
    unsigned long long w = g_pack[slot];
    #pragma unroll
    for (int s = 1; s < SPLITS; s++) {
        unsigned long long v = g_pack[slot + s];
        w = (v < w) ? v : w;
    }
    const float bb  = funmap((unsigned int)(w >> 32));
    const int  base = (int)(w & 0xFFFFFFFFu);

    const float qx = qb[qi*3+0], qy = qb[qi*3+1], qz = qb[qi*3+2];
    const float nqxv = -qx, nqyv = -qy, nqzv = -qz;

    int bi = base;
    #pragma unroll 4
    for (int j = 0; j < 32; j++) {
        int c = base + j;
        float d = score(dbb[c*3+0], dbb[c*3+1], dbb[c*3+2], nqxv, nqyv, nqzv);
        if (d == bb) { bi = c; break; }   // first exact match = first min
    }

    float nx = dbb[bi*3+0], ny = dbb[bi*3+1], nz = dbb[bi*3+2];
    float ax = fabsf(qx - nx), ay = fabsf(qy - ny), az = fabsf(qz - nz);
    float ax2 = ax * ax, ay2 = ay * ay, az2 = az * az;
    float v = ax2 * ax2 * ax + ay2 * ay2 * ay + az2 * az2 * az;

    __shared__ float red[256];
    red[threadIdx.x] = v;
    __syncthreads();
    #pragma unroll
    for (int stride = 128; stride >= 32; stride >>= 1) {
        if (threadIdx.x < stride) red[threadIdx.x] += red[threadIdx.x + stride];
        __syncthreads();
    }
    __shared__ bool s_last;
    if (threadIdx.x < 32) {
        float r = red[threadIdx.x];
        #pragma unroll
        for (int off = 16; off > 0; off >>= 1)
            r += __shfl_down_sync(0xFFFFFFFF, r, off);
        if (threadIdx.x == 0) {
            g_part[(dir * BATCH + b) * QCHUNKS + chunk] = r;
            __threadfence();
            unsigned int t = atomicAdd(&g_ticket, 1u);
            s_last = (t == NCOMBINE - 1);
        }
    }
    __syncthreads();

    if (s_last) {
        // Final reduction, fused into the last-arriving block.
        __shared__ float sp[NCOMBINE];
        __shared__ float roots[2 * BATCH];
        sp[threadIdx.x] = g_part[threadIdx.x];
        __syncthreads();
        if (threadIdx.x < 2 * BATCH) {
            float s = 0.0f;
            #pragma unroll
            for (int c = 0; c < QCHUNKS; c++) s += sp[threadIdx.x * QCHUNKS + c];
            roots[threadIdx.x] = powf(s, 0.2f);
        }
        __syncthreads();
        if (threadIdx.x == 0) {
            float acc = 0.0f;
            #pragma unroll
            for (int i = 0; i < 2 * BATCH; i++) acc += roots[i];
            out[0] = acc / (float)BATCH;
            g_ticket = 0;   // reset for next graph replay (deterministic)
        }
    }
}

extern "C" void kernel_launch(void* const* d_in, const int* in_sizes, int n_in,
                              void* d_out, int out_size)
{
    const float* x = (const float*)d_in[0];
    const float* y = (const float*)d_in[1];
    float* out = (float*)d_out;

    dim3 grid(QCHUNKS_MAIN * SPLITS, BATCH, 2);   // 128 x 8 x 2 = 2048 blocks
    chamfer_main<<<grid, BLOCK>>>(x, y);

    dim3 cgrid(QCHUNKS, BATCH, 2);                // 16 x 8 x 2 = 256 blocks
    combine_kernel<<<cgrid, 256>>>(x, y, out);
}